// round 10
// baseline (speedup 1.0000x reference)
#include <cuda_runtime.h>
#include <cuda_bf16.h>
#include <cstdint>

// ---------------- problem constants ----------------
#define NN    50000
#define INF   768
#define HH    128
#define RR    3
#define NSEG  (NN * RR)

typedef __nv_bfloat16 bf16;

// ---------------- scratch (device globals; no runtime alloc) ----------------
__device__ bf16  g_Bh[512 * INF];             // packed weights [512,K] bf16 hi
__device__ bf16  g_Bl[512 * INF];             // lo
__device__ bf16  g_Weh[256 * 128];            // edge W1 packed [256,128] hi
__device__ bf16  g_Wel[256 * 128];            // lo
__device__ bf16  g_xh[(size_t)NN * INF];      // activation hi (bf16)
__device__ bf16  g_xl[(size_t)NN * INF];      // activation lo
__device__ float g_hcomb[(size_t)NN * 512];   // GEMM out [N,512]; reused as UV [N,256]
__device__ float g_xb[(size_t)NN * HH];       // x3 fp32 (node head)
__device__ int   g_deg[NSEG];
__device__ int   g_offs[NSEG + 1];
__device__ int   g_cur[NSEG];
__device__ int   g_epack[800000 + 64];        // CSR edge data: src index (per (dst,rel) segment)

// ================= helpers =================
__device__ __forceinline__ uint32_t smem_u32(const void* p) {
    uint32_t a;
    asm("{ .reg .u64 t; cvta.to.shared.u64 t, %1; cvt.u32.u64 %0, t; }" : "=r"(a) : "l"(p));
    return a;
}
// L2-only policy: staged tiles are consumed exactly once from smem.
__device__ __forceinline__ void cpasync16(uint32_t saddr, const void* g) {
    asm volatile("cp.async.cg.shared.global [%0], [%1], 16;" :: "r"(saddr), "l"(g));
}
#define CP_COMMIT() asm volatile("cp.async.commit_group;" ::: "memory")
#define CP_WAIT1()  asm volatile("cp.async.wait_group 1;" ::: "memory")
#define CP_WAIT0()  asm volatile("cp.async.wait_group 0;" ::: "memory")

__device__ __forceinline__ void ldsm4(uint32_t (&r)[4], uint32_t addr) {
    asm volatile("ldmatrix.sync.aligned.m8n8.x4.shared.b16 {%0,%1,%2,%3}, [%4];"
                 : "=r"(r[0]), "=r"(r[1]), "=r"(r[2]), "=r"(r[3]) : "r"(addr));
}
__device__ __forceinline__ void mma_bf16(float (&d)[4], const uint32_t (&a)[4],
                                         uint32_t b0, uint32_t b1) {
    asm volatile("mma.sync.aligned.m16n8k16.row.col.f32.bf16.bf16.f32 "
                 "{%0,%1,%2,%3}, {%4,%5,%6,%7}, {%8,%9}, {%0,%1,%2,%3};"
                 : "+f"(d[0]), "+f"(d[1]), "+f"(d[2]), "+f"(d[3])
                 : "r"(a[0]), "r"(a[1]), "r"(a[2]), "r"(a[3]), "r"(b0), "r"(b1));
}

// smem tile: 128 rows x 4 chunks of 16B. XOR swizzle.
__device__ __forceinline__ uint32_t swz(int row, int chunk) {
    return (uint32_t)(((row << 2) + (chunk ^ ((row >> 1) & 3))) << 4);
}
#define TILE_B  8192
#define STAGE_B (4 * TILE_B)
#define NSTAGE  3
#define DYN_SMEM (NSTAGE * STAGE_B)    // 96 KB

// ---------------- stage loader ----------------
__device__ __forceinline__ void load_stage_dense(
    uint32_t sb, const bf16* __restrict__ Ah, const bf16* __restrict__ Al,
    const bf16* __restrict__ Bh, const bf16* __restrict__ Bl,
    int K, int bm, int n0, int k0, int M, int tid) {
#pragma unroll
    for (int i = 0; i < 2; i++) {
        int cid = tid * 2 + i;
        int row = cid >> 2, ch = cid & 3;
        int gm = bm + row; if (gm >= M) gm = M - 1;
        size_t ga = (size_t)gm * K + k0 + ch * 8;
        uint32_t so = swz(row, ch);
        cpasync16(sb + so, Ah + ga);
        cpasync16(sb + TILE_B + so, Al + ga);
        size_t gb = (size_t)(n0 + row) * K + k0 + ch * 8;
        cpasync16(sb + 2 * TILE_B + so, Bh + gb);
        cpasync16(sb + 3 * TILE_B + so, Bl + gb);
    }
}

// ---------------- warp-tile compute (64x32, bf16x3) ----------------
__device__ __forceinline__ void compute_stage(float (&acc)[4][4][4], uint32_t sb,
                                              int m0w, int n0w, int lane) {
#pragma unroll
    for (int kf = 0; kf < 2; kf++) {
        uint32_t ah[4][4], al[4][4], bh[2][4], bl[2][4];
        const int arow = lane & 15;
        const int ach = kf * 2 + (lane >> 4);
        const int brow = n0w + ((lane >> 4) << 3) + (lane & 7);
        const int bch = kf * 2 + ((lane >> 3) & 1);
#pragma unroll
        for (int mf = 0; mf < 4; mf++)
            ldsm4(ah[mf], sb + swz(m0w + mf * 16 + arow, ach));
#pragma unroll
        for (int p = 0; p < 2; p++)
            ldsm4(bh[p], sb + 2 * TILE_B + swz(brow + p * 16, bch));
#pragma unroll
        for (int mf = 0; mf < 4; mf++)
#pragma unroll
            for (int nf = 0; nf < 4; nf++)
                mma_bf16(acc[mf][nf], ah[mf], bh[nf >> 1][(nf & 1) * 2], bh[nf >> 1][(nf & 1) * 2 + 1]);
#pragma unroll
        for (int p = 0; p < 2; p++)
            ldsm4(bl[p], sb + 3 * TILE_B + swz(brow + p * 16, bch));
#pragma unroll
        for (int mf = 0; mf < 4; mf++)
#pragma unroll
            for (int nf = 0; nf < 4; nf++)
                mma_bf16(acc[mf][nf], ah[mf], bl[nf >> 1][(nf & 1) * 2], bl[nf >> 1][(nf & 1) * 2 + 1]);
#pragma unroll
        for (int mf = 0; mf < 4; mf++)
            ldsm4(al[mf], sb + TILE_B + swz(m0w + mf * 16 + arow, ach));
#pragma unroll
        for (int mf = 0; mf < 4; mf++)
#pragma unroll
            for (int nf = 0; nf < 4; nf++)
                mma_bf16(acc[mf][nf], al[mf], bh[nf >> 1][(nf & 1) * 2], bh[nf >> 1][(nf & 1) * 2 + 1]);
    }
}

// ---------------- GEMM: 3-stage cp.async pipeline ----------------
__global__ __launch_bounds__(256)
void gemm_mma(const bf16* __restrict__ Ah, const bf16* __restrict__ Al,
              const bf16* __restrict__ Bh, const bf16* __restrict__ Bl,
              float* __restrict__ C, int M, int K, int ldc) {
    extern __shared__ char dsm[];
    const uint32_t sb = smem_u32(dsm);
    const int tid = threadIdx.x, lane = tid & 31, wid = tid >> 5;
    const int bm = blockIdx.y * 128, n0 = blockIdx.x * 128;
    const int m0w = (wid >> 2) * 64, n0w = (wid & 3) * 32;
    float acc[4][4][4];
#pragma unroll
    for (int a = 0; a < 4; a++)
#pragma unroll
        for (int b = 0; b < 4; b++)
#pragma unroll
            for (int c = 0; c < 4; c++) acc[a][b][c] = 0.f;

    const int niter = K / 32;   // always >= 2 here
    load_stage_dense(sb, Ah, Al, Bh, Bl, K, bm, n0, 0, M, tid);
    CP_COMMIT();
    load_stage_dense(sb + STAGE_B, Ah, Al, Bh, Bl, K, bm, n0, 32, M, tid);
    CP_COMMIT();

    int buf = 0;
    for (int it = 0; it < niter; it++) {
        if (it + 1 < niter) CP_WAIT1(); else CP_WAIT0();
        __syncthreads();
        if (it + 2 < niter) {
            int nb = buf + 2; if (nb >= NSTAGE) nb -= NSTAGE;
            load_stage_dense(sb + nb * STAGE_B, Ah, Al, Bh, Bl, K, bm, n0, (it + 2) * 32, M, tid);
            CP_COMMIT();
        }
        compute_stage(acc, sb + buf * STAGE_B, m0w, n0w, lane);
        if (++buf == NSTAGE) buf = 0;
    }

#pragma unroll
    for (int mf = 0; mf < 4; mf++) {
#pragma unroll
        for (int nf = 0; nf < 4; nf++) {
            int col = n0 + n0w + nf * 8 + (lane & 3) * 2;
            int r0 = bm + m0w + mf * 16 + (lane >> 2);
            if (r0 < M)
                *(float2*)&C[(size_t)r0 * ldc + col] = make_float2(acc[mf][nf][0], acc[mf][nf][1]);
            int r1 = r0 + 8;
            if (r1 < M)
                *(float2*)&C[(size_t)r1 * ldc + col] = make_float2(acc[mf][nf][2], acc[mf][nf][3]);
        }
    }
}

// ---------------- CSR build: segmented by (dst, rel) ----------------
__global__ void deg_kernel(const int* __restrict__ dst, const int* __restrict__ et,
                           int* __restrict__ deg, int E) {
    int i = blockIdx.x * blockDim.x + threadIdx.x;
    if (i < E) atomicAdd(&deg[dst[i] * RR + et[i]], 1);
}

__global__ void scan_kernel(const int* __restrict__ deg, int* __restrict__ offs) {
    __shared__ int warp_sums[32];
    __shared__ int s_carry;
    const int t = threadIdx.x;          // 1024 threads, single block
    const int lane = t & 31, w = t >> 5;
    if (t == 0) { s_carry = 0; offs[0] = 0; }
    __syncthreads();
    for (int base = 0; base < NSEG; base += 1024) {
        int v = (base + t < NSEG) ? deg[base + t] : 0;
        int x = v;
#pragma unroll
        for (int o = 1; o < 32; o <<= 1) {
            int y = __shfl_up_sync(0xFFFFFFFFu, x, o);
            if (lane >= o) x += y;
        }
        if (lane == 31) warp_sums[w] = x;
        __syncthreads();
        if (w == 0) {
            int s = warp_sums[lane];
#pragma unroll
            for (int o = 1; o < 32; o <<= 1) {
                int y = __shfl_up_sync(0xFFFFFFFFu, s, o);
                if (lane >= o) s += y;
            }
            warp_sums[lane] = s;
        }
        __syncthreads();
        int incl = x + (w > 0 ? warp_sums[w - 1] : 0) + s_carry;
        if (base + t < NSEG) offs[base + t + 1] = incl;
        __syncthreads();
        if (t == 1023) s_carry = incl;
        __syncthreads();
    }
}

__global__ void fill_kernel(const int* __restrict__ src, const int* __restrict__ dst,
                            const int* __restrict__ et, const int* __restrict__ offs,
                            int* __restrict__ cur, int* __restrict__ epack, int E) {
    int i = blockIdx.x * blockDim.x + threadIdx.x;
    if (i >= E) return;
    int seg = dst[i] * RR + et[i];
    int p = atomicAdd(&cur[seg], 1);
    epack[offs[seg] + p] = src[i];
}

// ---------------- fused aggregation: warp/node, branch-free per-relation loops ----------------
__global__ __launch_bounds__(256)
void agg_combine(const float* __restrict__ hcomb, const int* __restrict__ offs,
                 const int* __restrict__ epack, const float* __restrict__ b,
                 float* __restrict__ xb, bf16* __restrict__ xh, bf16* __restrict__ xl,
                 int do_relu, int write_f32) {
    int node = (blockIdx.x * blockDim.x + threadIdx.x) >> 5;
    int lane = threadIdx.x & 31;
    if (node >= NN) return;

    float4 root = *(const float4*)&hcomb[(size_t)node * 512 + lane * 4];
    float4 bb = *(const float4*)&b[lane * 4];
    float tx = root.x + bb.x, ty = root.y + bb.y;
    float tz = root.z + bb.z, tw = root.w + bb.w;

#pragma unroll
    for (int r = 0; r < RR; r++) {
        const int o0 = offs[node * RR + r];
        const int o1 = offs[node * RR + r + 1];
        const float* __restrict__ hb = hcomb + 128 + (r << 7) + lane * 4;
        float sx = 0.f, sy = 0.f, sz = 0.f, sw = 0.f;
        int e = o0;
        for (; e + 4 <= o1; e += 4) {
            int s0 = __ldg(&epack[e + 0]);
            int s1 = __ldg(&epack[e + 1]);
            int s2 = __ldg(&epack[e + 2]);
            int s3 = __ldg(&epack[e + 3]);
            float4 v0 = __ldg((const float4*)(hb + (size_t)s0 * 512));
            float4 v1 = __ldg((const float4*)(hb + (size_t)s1 * 512));
            float4 v2 = __ldg((const float4*)(hb + (size_t)s2 * 512));
            float4 v3 = __ldg((const float4*)(hb + (size_t)s3 * 512));
            sx += v0.x + v1.x + v2.x + v3.x;
            sy += v0.y + v1.y + v2.y + v3.y;
            sz += v0.z + v1.z + v2.z + v3.z;
            sw += v0.w + v1.w + v2.w + v3.w;
        }
        for (; e < o1; e++) {
            int s0 = __ldg(&epack[e]);
            float4 v0 = __ldg((const float4*)(hb + (size_t)s0 * 512));
            sx += v0.x; sy += v0.y; sz += v0.z; sw += v0.w;
        }
        float inv = 1.f / (float)max(o1 - o0, 1);
        tx += sx * inv; ty += sy * inv; tz += sz * inv; tw += sw * inv;
    }

    if (do_relu) {
        tx = fmaxf(tx, 0.f); ty = fmaxf(ty, 0.f);
        tz = fmaxf(tz, 0.f); tw = fmaxf(tw, 0.f);
    }
    size_t idx = (size_t)node * HH + lane * 4;
    if (write_f32) *(float4*)&xb[idx] = make_float4(tx, ty, tz, tw);
    bf16 h0 = __float2bfloat16(tx), h1 = __float2bfloat16(ty);
    bf16 h2 = __float2bfloat16(tz), h3 = __float2bfloat16(tw);
    __nv_bfloat162 hh0(h0, h1), hh1(h2, h3);
    *(uint2*)&xh[idx] = make_uint2(*(uint32_t*)&hh0, *(uint32_t*)&hh1);
    __nv_bfloat162 ll0(__float2bfloat16(tx - __bfloat162float(h0)),
                       __float2bfloat16(ty - __bfloat162float(h1)));
    __nv_bfloat162 ll1(__float2bfloat16(tz - __bfloat162float(h2)),
                       __float2bfloat16(tw - __bfloat162float(h3)));
    *(uint2*)&xl[idx] = make_uint2(*(uint32_t*)&ll0, *(uint32_t*)&ll1);
}

// ---------------- edge apply: warp/edge, relu(U[src]+V[dst]+be1) @ We2 + be2 ----------------
__global__ __launch_bounds__(256)
void edge_apply(const float* __restrict__ UV,
                const int* __restrict__ src, const int* __restrict__ dst,
                const float* __restrict__ be1, const float* __restrict__ We2,
                const float* __restrict__ be2, float* __restrict__ out, int E) {
    __shared__ float sBe1[128];
    __shared__ float sW2[384];
    const int tid = threadIdx.x, lane = tid & 31;
    if (tid < 128) sBe1[tid] = be1[tid];
    for (int v = tid; v < 384; v += 256) sW2[v] = We2[v];
    __syncthreads();
    int gw = (blockIdx.x * 256 + tid) >> 5;
    if (gw >= E) return;
    int s = src[gw], d = dst[gw];
    float4 u = __ldg((const float4*)(UV + (size_t)s * 256 + lane * 4));
    float4 v = __ldg((const float4*)(UV + (size_t)d * 256 + 128 + lane * 4));
    int c = lane * 4;
    float a0 = 0.f, a1 = 0.f, a2 = 0.f;
    float h;
    h = fmaxf(u.x + v.x + sBe1[c + 0], 0.f); a0 += h * sW2[(c + 0) * 3]; a1 += h * sW2[(c + 0) * 3 + 1]; a2 += h * sW2[(c + 0) * 3 + 2];
    h = fmaxf(u.y + v.y + sBe1[c + 1], 0.f); a0 += h * sW2[(c + 1) * 3]; a1 += h * sW2[(c + 1) * 3 + 1]; a2 += h * sW2[(c + 1) * 3 + 2];
    h = fmaxf(u.z + v.z + sBe1[c + 2], 0.f); a0 += h * sW2[(c + 2) * 3]; a1 += h * sW2[(c + 2) * 3 + 1]; a2 += h * sW2[(c + 2) * 3 + 2];
    h = fmaxf(u.w + v.w + sBe1[c + 3], 0.f); a0 += h * sW2[(c + 3) * 3]; a1 += h * sW2[(c + 3) * 3 + 1]; a2 += h * sW2[(c + 3) * 3 + 2];
#pragma unroll
    for (int o = 16; o; o >>= 1) {
        a0 += __shfl_xor_sync(0xFFFFFFFFu, a0, o);
        a1 += __shfl_xor_sync(0xFFFFFFFFu, a1, o);
        a2 += __shfl_xor_sync(0xFFFFFFFFu, a2, o);
    }
    if (lane == 0) {
        out[(size_t)gw * 3 + 0] = a0 + __ldg(&be2[0]);
        out[(size_t)gw * 3 + 1] = a1 + __ldg(&be2[1]);
        out[(size_t)gw * 3 + 2] = a2 + __ldg(&be2[2]);
    }
}

// ---------------- split fp32 -> bf16 hi/lo (layer-1 input only) ----------------
__global__ void split_bf16(const float* __restrict__ in, bf16* __restrict__ hi,
                           bf16* __restrict__ lo, int n4) {
    int i = blockIdx.x * blockDim.x + threadIdx.x;
    if (i >= n4) return;
    float4 v = ((const float4*)in)[i];
    bf16 h0 = __float2bfloat16(v.x), h1 = __float2bfloat16(v.y);
    bf16 h2 = __float2bfloat16(v.z), h3 = __float2bfloat16(v.w);
    ((__nv_bfloat162*)hi)[i * 2]     = __nv_bfloat162(h0, h1);
    ((__nv_bfloat162*)hi)[i * 2 + 1] = __nv_bfloat162(h2, h3);
    ((__nv_bfloat162*)lo)[i * 2]     = __nv_bfloat162(__float2bfloat16(v.x - __bfloat162float(h0)),
                                                      __float2bfloat16(v.y - __bfloat162float(h1)));
    ((__nv_bfloat162*)lo)[i * 2 + 1] = __nv_bfloat162(__float2bfloat16(v.z - __bfloat162float(h2)),
                                                      __float2bfloat16(v.w - __bfloat162float(h3)));
}

// ---------------- weight packing ----------------
__global__ void pack_layer(const float* __restrict__ W_root, const float* __restrict__ W_rel,
                           bf16* __restrict__ Bh, bf16* __restrict__ Bl, int K) {
    int idx = blockIdx.x * blockDim.x + threadIdx.x;
    if (idx >= 512 * K) return;
    int n = idx / K, k = idx % K;
    float v;
    if (n < HH) v = W_root[k * HH + n];
    else        v = W_rel[((size_t)((n >> 7) - 1) * K + k) * HH + (n & 127)];
    bf16 h = __float2bfloat16(v);
    Bh[idx] = h;
    Bl[idx] = __float2bfloat16(v - __bfloat162float(h));
}
__global__ void pack_edge(const float* __restrict__ We1, bf16* __restrict__ Bh,
                          bf16* __restrict__ Bl) {
    int idx = blockIdx.x * blockDim.x + threadIdx.x;
    if (idx >= 256 * 128) return;
    int n = idx / 128, k = idx % 128;
    float v = (n < 128) ? We1[k * 128 + n] : We1[(128 + k) * 128 + (n - 128)];
    bf16 h = __float2bfloat16(v);
    Bh[idx] = h;
    Bl[idx] = __float2bfloat16(v - __bfloat162float(h));
}

// ---------------- node head: 64 nodes/block, weights in smem ----------------
__global__ __launch_bounds__(256)
void node_head_kernel(const float* __restrict__ x3, const float* __restrict__ Wn1,
                      const float* __restrict__ bn1, const float* __restrict__ Wn2,
                      const float* __restrict__ bn2, float* __restrict__ out) {
    __shared__ float sW1[128 * 64];
    __shared__ float sb1[64];
    __shared__ float sW2[128];
    __shared__ float sx[4][128];
    __shared__ float sPart[8][2];
    const int tid = threadIdx.x;
    const int team = tid >> 6, t = tid & 63;      // 4 teams of 64
    const int wid = tid >> 5, lane = tid & 31;
    for (int i = tid; i < 128 * 64; i += 256) sW1[i] = Wn1[i];
    if (tid < 64) sb1[tid] = bn1[tid];
    if (tid < 128) sW2[tid] = Wn2[tid];
    float b20 = __ldg(&bn2[0]), b21 = __ldg(&bn2[1]);
    __syncthreads();
    const int base = blockIdx.x * 64;
#pragma unroll 1
    for (int it = 0; it < 16; it++) {
        int node = base + it * 4 + team;
        bool ok = node < NN;
        if (ok) {
            sx[team][t]      = x3[(size_t)node * HH + t];
            sx[team][t + 64] = x3[(size_t)node * HH + t + 64];
        }
        __syncthreads();
        float p0 = 0.f, p1 = 0.f;
        if (ok) {
            float acc = sb1[t];
#pragma unroll
            for (int k = 0; k < 128; k++) acc += sx[team][k] * sW1[k * 64 + t];
            float hgt = fmaxf(acc, 0.f);
            p0 = hgt * sW2[t * 2 + 0];
            p1 = hgt * sW2[t * 2 + 1];
        }
#pragma unroll
        for (int o = 16; o; o >>= 1) {
            p0 += __shfl_xor_sync(0xFFFFFFFFu, p0, o);
            p1 += __shfl_xor_sync(0xFFFFFFFFu, p1, o);
        }
        if (lane == 0) { sPart[wid][0] = p0; sPart[wid][1] = p1; }
        __syncthreads();
        if (ok && t == 0) {
            out[(size_t)node * 2 + 0] = sPart[team * 2][0] + sPart[team * 2 + 1][0] + b20;
            out[(size_t)node * 2 + 1] = sPart[team * 2][1] + sPart[team * 2 + 1][1] + b21;
        }
        __syncthreads();
    }
}

// ---------------- launch ----------------
extern "C" void kernel_launch(void* const* d_in, const int* in_sizes, int n_in,
                              void* d_out, int out_size) {
    const float* x       = (const float*)d_in[0];
    const int*   ei      = (const int*)d_in[1];
    const int*   et      = (const int*)d_in[2];
    const float* W_rel1  = (const float*)d_in[3];
    const float* W_root1 = (const float*)d_in[4];
    const float* b1      = (const float*)d_in[5];
    const float* W_rel2  = (const float*)d_in[6];
    const float* W_root2 = (const float*)d_in[7];
    const float* b2      = (const float*)d_in[8];
    const float* W_rel3  = (const float*)d_in[9];
    const float* W_root3 = (const float*)d_in[10];
    const float* b3      = (const float*)d_in[11];
    const float* We1     = (const float*)d_in[12];
    const float* be1     = (const float*)d_in[13];
    const float* We2     = (const float*)d_in[14];
    const float* be2     = (const float*)d_in[15];
    const float* Wn1     = (const float*)d_in[16];
    const float* bn1     = (const float*)d_in[17];
    const float* Wn2     = (const float*)d_in[18];
    const float* bn2     = (const float*)d_in[19];

    const int E = in_sizes[2];
    const int* src = ei;
    const int* dst = ei + E;

    bf16 *Bh, *Bl, *Weh, *Wel, *xh, *xl;
    float *hcomb, *xb;
    int *deg, *offs, *cur, *epack;
    cudaGetSymbolAddress((void**)&Bh, g_Bh);
    cudaGetSymbolAddress((void**)&Bl, g_Bl);
    cudaGetSymbolAddress((void**)&Weh, g_Weh);
    cudaGetSymbolAddress((void**)&Wel, g_Wel);
    cudaGetSymbolAddress((void**)&xh, g_xh);
    cudaGetSymbolAddress((void**)&xl, g_xl);
    cudaGetSymbolAddress((void**)&hcomb, g_hcomb);
    cudaGetSymbolAddress((void**)&xb, g_xb);
    cudaGetSymbolAddress((void**)&deg, g_deg);
    cudaGetSymbolAddress((void**)&offs, g_offs);
    cudaGetSymbolAddress((void**)&cur, g_cur);
    cudaGetSymbolAddress((void**)&epack, g_epack);

    cudaFuncSetAttribute(gemm_mma, cudaFuncAttributeMaxDynamicSharedMemorySize, DYN_SMEM);

    float* out = (float*)d_out;
    float* edge_out = out;
    float* node_out = out + (size_t)E * 3;

    const int aggBlocks = (NN * 32 + 255) / 256;
    dim3 gemmGrid(4, (NN + 127) / 128);
    dim3 uvGrid(2, (NN + 127) / 128);

    // ---- CSR build (once), segmented by (dst, rel) ----
    cudaMemsetAsync(deg, 0, NSEG * sizeof(int));
    cudaMemsetAsync(cur, 0, NSEG * sizeof(int));
    deg_kernel<<<(E + 255) / 256, 256>>>(dst, et, deg, E);
    scan_kernel<<<1, 1024>>>(deg, offs);
    fill_kernel<<<(E + 255) / 256, 256>>>(src, dst, et, offs, cur, epack, E);

    // ---- layer 1 ----
    split_bf16<<<(NN * INF / 4 + 255) / 256, 256>>>(x, xh, xl, NN * INF / 4);
    pack_layer<<<(512 * INF + 255) / 256, 256>>>(W_root1, W_rel1, Bh, Bl, INF);
    gemm_mma<<<gemmGrid, 256, DYN_SMEM>>>(xh, xl, Bh, Bl, hcomb, NN, INF, 512);
    agg_combine<<<aggBlocks, 256>>>(hcomb, offs, epack, b1, xb, xh, xl, 1, 0);

    // ---- layer 2 ----
    pack_layer<<<(512 * HH + 255) / 256, 256>>>(W_root2, W_rel2, Bh, Bl, HH);
    gemm_mma<<<gemmGrid, 256, DYN_SMEM>>>(xh, xl, Bh, Bl, hcomb, NN, HH, 512);
    agg_combine<<<aggBlocks, 256>>>(hcomb, offs, epack, b2, xb, xh, xl, 1, 0);

    // ---- layer 3 (no relu; keep fp32 for node head) ----
    pack_layer<<<(512 * HH + 255) / 256, 256>>>(W_root3, W_rel3, Bh, Bl, HH);
    gemm_mma<<<gemmGrid, 256, DYN_SMEM>>>(xh, xl, Bh, Bl, hcomb, NN, HH, 512);
    agg_combine<<<aggBlocks, 256>>>(hcomb, offs, epack, b3, xb, xh, xl, 0, 1);

    // ---- edge head: UV = x3 @ [We1_top|We1_bot], then per-edge apply ----
    pack_edge<<<(256 * 128 + 255) / 256, 256>>>(We1, Weh, Wel);
    gemm_mma<<<uvGrid, 256, DYN_SMEM>>>(xh, xl, Weh, Wel, hcomb, NN, HH, 256);
    edge_apply<<<(E * 32 + 255) / 256, 256>>>(hcomb, src, dst, be1, We2, be2, edge_out, E);

    // ---- node head ----
    node_head_kernel<<<(NN + 63) / 64, 256>>>(xb, Wn1, bn1, Wn2, bn2, node_out);
}

// round 11
// speedup vs baseline: 1.0602x; 1.0602x over previous
#include <cuda_runtime.h>
#include <cuda_bf16.h>
#include <cstdint>

// ---------------- problem constants ----------------
#define NN    50000
#define INF   768
#define HH    128
#define RR    3

typedef __nv_bfloat16 bf16;

// ---------------- scratch (device globals; no runtime alloc) ----------------
__device__ bf16  g_B1h[512 * INF];
__device__ bf16  g_B1l[512 * INF];
__device__ bf16  g_B2h[512 * HH];
__device__ bf16  g_B2l[512 * HH];
__device__ bf16  g_B3h[512 * HH];
__device__ bf16  g_B3l[512 * HH];
__device__ bf16  g_Weh[256 * 128];
__device__ bf16  g_Wel[256 * 128];
__device__ bf16  g_xh[(size_t)NN * INF];      // activation hi (bf16)
__device__ bf16  g_xl[(size_t)NN * INF];      // activation lo
__device__ float g_hcomb[(size_t)NN * 512];   // GEMM out [N,512]; reused as UV [N,256]
__device__ float g_xb[(size_t)NN * HH];       // x3 fp32 (node head)
__device__ int   g_deg[NN];
__device__ int   g_offs[NN + 1];
__device__ int   g_cur[NN];
__device__ int   g_cnt3[NN * RR];
__device__ int   g_epack[800000 + 64];        // CSR edge data: src | et<<28

// ================= helpers =================
__device__ __forceinline__ uint32_t smem_u32(const void* p) {
    uint32_t a;
    asm("{ .reg .u64 t; cvta.to.shared.u64 t, %1; cvt.u32.u64 %0, t; }" : "=r"(a) : "l"(p));
    return a;
}
// L2-only policy: staged tiles are consumed exactly once from smem.
__device__ __forceinline__ void cpasync16(uint32_t saddr, const void* g) {
    asm volatile("cp.async.cg.shared.global [%0], [%1], 16;" :: "r"(saddr), "l"(g));
}
#define CP_COMMIT() asm volatile("cp.async.commit_group;" ::: "memory")
#define CP_WAIT1()  asm volatile("cp.async.wait_group 1;" ::: "memory")
#define CP_WAIT0()  asm volatile("cp.async.wait_group 0;" ::: "memory")

__device__ __forceinline__ void ldsm4(uint32_t (&r)[4], uint32_t addr) {
    asm volatile("ldmatrix.sync.aligned.m8n8.x4.shared.b16 {%0,%1,%2,%3}, [%4];"
                 : "=r"(r[0]), "=r"(r[1]), "=r"(r[2]), "=r"(r[3]) : "r"(addr));
}
__device__ __forceinline__ void mma_bf16(float (&d)[4], const uint32_t (&a)[4],
                                         uint32_t b0, uint32_t b1) {
    asm volatile("mma.sync.aligned.m16n8k16.row.col.f32.bf16.bf16.f32 "
                 "{%0,%1,%2,%3}, {%4,%5,%6,%7}, {%8,%9}, {%0,%1,%2,%3};"
                 : "+f"(d[0]), "+f"(d[1]), "+f"(d[2]), "+f"(d[3])
                 : "r"(a[0]), "r"(a[1]), "r"(a[2]), "r"(a[3]), "r"(b0), "r"(b1));
}

// smem tile: 128 rows x 4 chunks of 16B. XOR swizzle.
__device__ __forceinline__ uint32_t swz(int row, int chunk) {
    return (uint32_t)(((row << 2) + (chunk ^ ((row >> 1) & 3))) << 4);
}
#define TILE_B  8192
#define STAGE_B (4 * TILE_B)
#define NSTAGE  3
#define DYN_SMEM (NSTAGE * STAGE_B)    // 96 KB

// ---------------- stage loader ----------------
__device__ __forceinline__ void load_stage_dense(
    uint32_t sb, const bf16* __restrict__ Ah, const bf16* __restrict__ Al,
    const bf16* __restrict__ Bh, const bf16* __restrict__ Bl,
    int K, int bm, int n0, int k0, int M, int tid) {
#pragma unroll
    for (int i = 0; i < 2; i++) {
        int cid = tid * 2 + i;
        int row = cid >> 2, ch = cid & 3;
        int gm = bm + row; if (gm >= M) gm = M - 1;
        size_t ga = (size_t)gm * K + k0 + ch * 8;
        uint32_t so = swz(row, ch);
        cpasync16(sb + so, Ah + ga);
        cpasync16(sb + TILE_B + so, Al + ga);
        size_t gb = (size_t)(n0 + row) * K + k0 + ch * 8;
        cpasync16(sb + 2 * TILE_B + so, Bh + gb);
        cpasync16(sb + 3 * TILE_B + so, Bl + gb);
    }
}

// ---------------- warp-tile compute (64x32, bf16x3) ----------------
__device__ __forceinline__ void compute_stage(float (&acc)[4][4][4], uint32_t sb,
                                              int m0w, int n0w, int lane) {
#pragma unroll
    for (int kf = 0; kf < 2; kf++) {
        uint32_t ah[4][4], al[4][4], bh[2][4], bl[2][4];
        const int arow = lane & 15;
        const int ach = kf * 2 + (lane >> 4);
        const int brow = n0w + ((lane >> 4) << 3) + (lane & 7);
        const int bch = kf * 2 + ((lane >> 3) & 1);
#pragma unroll
        for (int mf = 0; mf < 4; mf++)
            ldsm4(ah[mf], sb + swz(m0w + mf * 16 + arow, ach));
#pragma unroll
        for (int p = 0; p < 2; p++)
            ldsm4(bh[p], sb + 2 * TILE_B + swz(brow + p * 16, bch));
#pragma unroll
        for (int mf = 0; mf < 4; mf++)
#pragma unroll
            for (int nf = 0; nf < 4; nf++)
                mma_bf16(acc[mf][nf], ah[mf], bh[nf >> 1][(nf & 1) * 2], bh[nf >> 1][(nf & 1) * 2 + 1]);
#pragma unroll
        for (int p = 0; p < 2; p++)
            ldsm4(bl[p], sb + 3 * TILE_B + swz(brow + p * 16, bch));
#pragma unroll
        for (int mf = 0; mf < 4; mf++)
#pragma unroll
            for (int nf = 0; nf < 4; nf++)
                mma_bf16(acc[mf][nf], ah[mf], bl[nf >> 1][(nf & 1) * 2], bl[nf >> 1][(nf & 1) * 2 + 1]);
#pragma unroll
        for (int mf = 0; mf < 4; mf++)
            ldsm4(al[mf], sb + TILE_B + swz(m0w + mf * 16 + arow, ach));
#pragma unroll
        for (int mf = 0; mf < 4; mf++)
#pragma unroll
            for (int nf = 0; nf < 4; nf++)
                mma_bf16(acc[mf][nf], al[mf], bh[nf >> 1][(nf & 1) * 2], bh[nf >> 1][(nf & 1) * 2 + 1]);
    }
}

// ---------------- GEMM: 3-stage cp.async pipeline ----------------
__global__ __launch_bounds__(256)
void gemm_mma(const bf16* __restrict__ Ah, const bf16* __restrict__ Al,
              const bf16* __restrict__ Bh, const bf16* __restrict__ Bl,
              float* __restrict__ C, int M, int K, int ldc) {
    extern __shared__ char dsm[];
    const uint32_t sb = smem_u32(dsm);
    const int tid = threadIdx.x, lane = tid & 31, wid = tid >> 5;
    const int bm = blockIdx.y * 128, n0 = blockIdx.x * 128;
    const int m0w = (wid >> 2) * 64, n0w = (wid & 3) * 32;
    float acc[4][4][4];
#pragma unroll
    for (int a = 0; a < 4; a++)
#pragma unroll
        for (int b = 0; b < 4; b++)
#pragma unroll
            for (int c = 0; c < 4; c++) acc[a][b][c] = 0.f;

    const int niter = K / 32;   // always >= 2 here
    load_stage_dense(sb, Ah, Al, Bh, Bl, K, bm, n0, 0, M, tid);
    CP_COMMIT();
    load_stage_dense(sb + STAGE_B, Ah, Al, Bh, Bl, K, bm, n0, 32, M, tid);
    CP_COMMIT();

    int buf = 0;
    for (int it = 0; it < niter; it++) {
        if (it + 1 < niter) CP_WAIT1(); else CP_WAIT0();
        __syncthreads();
        if (it + 2 < niter) {
            int nb = buf + 2; if (nb >= NSTAGE) nb -= NSTAGE;
            load_stage_dense(sb + nb * STAGE_B, Ah, Al, Bh, Bl, K, bm, n0, (it + 2) * 32, M, tid);
            CP_COMMIT();
        }
        compute_stage(acc, sb + buf * STAGE_B, m0w, n0w, lane);
        if (++buf == NSTAGE) buf = 0;
    }

#pragma unroll
    for (int mf = 0; mf < 4; mf++) {
#pragma unroll
        for (int nf = 0; nf < 4; nf++) {
            int col = n0 + n0w + nf * 8 + (lane & 3) * 2;
            int r0 = bm + m0w + mf * 16 + (lane >> 2);
            if (r0 < M)
                *(float2*)&C[(size_t)r0 * ldc + col] = make_float2(acc[mf][nf][0], acc[mf][nf][1]);
            int r1 = r0 + 8;
            if (r1 < M)
                *(float2*)&C[(size_t)r1 * ldc + col] = make_float2(acc[mf][nf][2], acc[mf][nf][3]);
        }
    }
}

// ---------------- CSR build (by dst) + per-(dst,rel) counts ----------------
__global__ void deg_kernel(const int* __restrict__ dst, const int* __restrict__ et,
                           int* __restrict__ deg, int* __restrict__ cnt3, int E) {
    int i = blockIdx.x * blockDim.x + threadIdx.x;
    if (i >= E) return;
    int d = dst[i];
    atomicAdd(&deg[d], 1);
    atomicAdd(&cnt3[d * RR + et[i]], 1);
}

__global__ void scan_kernel(const int* __restrict__ deg, int* __restrict__ offs) {
    __shared__ int warp_sums[32];
    __shared__ int s_carry;
    const int t = threadIdx.x;          // 1024 threads, single block
    const int lane = t & 31, w = t >> 5;
    if (t == 0) { s_carry = 0; offs[0] = 0; }
    __syncthreads();
    for (int base = 0; base < NN; base += 1024) {
        int v = (base + t < NN) ? deg[base + t] : 0;
        int x = v;
#pragma unroll
        for (int o = 1; o < 32; o <<= 1) {
            int y = __shfl_up_sync(0xFFFFFFFFu, x, o);
            if (lane >= o) x += y;
        }
        if (lane == 31) warp_sums[w] = x;
        __syncthreads();
        if (w == 0) {
            int s = warp_sums[lane];
#pragma unroll
            for (int o = 1; o < 32; o <<= 1) {
                int y = __shfl_up_sync(0xFFFFFFFFu, s, o);
                if (lane >= o) s += y;
            }
            warp_sums[lane] = s;
        }
        __syncthreads();
        int incl = x + (w > 0 ? warp_sums[w - 1] : 0) + s_carry;
        if (base + t < NN) offs[base + t + 1] = incl;
        __syncthreads();
        if (t == 1023) s_carry = incl;
        __syncthreads();
    }
}

__global__ void fill_kernel(const int* __restrict__ src, const int* __restrict__ dst,
                            const int* __restrict__ et, const int* __restrict__ offs,
                            int* __restrict__ cur, int* __restrict__ epack, int E) {
    int i = blockIdx.x * blockDim.x + threadIdx.x;
    if (i >= E) return;
    int d = dst[i];
    int p = atomicAdd(&cur[d], 1);
    epack[offs[d] + p] = src[i] | (et[i] << 28);
}

// ---------------- fused aggregation: warp/node, branch-free weighted sum ----------------
__global__ __launch_bounds__(256)
void agg_combine(const float* __restrict__ hcomb, const int* __restrict__ offs,
                 const int* __restrict__ epack, const int* __restrict__ cnt3,
                 const float* __restrict__ b,
                 float* __restrict__ xb, bf16* __restrict__ xh, bf16* __restrict__ xl,
                 int do_relu, int write_f32) {
    int node = (blockIdx.x * blockDim.x + threadIdx.x) >> 5;
    int lane = threadIdx.x & 31;
    if (node >= NN) return;
    const int o0 = offs[node], o1 = offs[node + 1];
    const float w0 = 1.f / (float)max(__ldg(&cnt3[node * RR + 0]), 1);
    const float w1 = 1.f / (float)max(__ldg(&cnt3[node * RR + 1]), 1);
    const float w2 = 1.f / (float)max(__ldg(&cnt3[node * RR + 2]), 1);

    float4 root = *(const float4*)&hcomb[(size_t)node * 512 + lane * 4];
    float4 bb = *(const float4*)&b[lane * 4];
    float tx = root.x + bb.x, ty = root.y + bb.y;
    float tz = root.z + bb.z, tw = root.w + bb.w;

    const float* __restrict__ hb = hcomb + 128 + lane * 4;
    int e = o0;
    for (; e + 4 <= o1; e += 4) {
        int p0 = __ldg(&epack[e + 0]);
        int p1 = __ldg(&epack[e + 1]);
        int p2 = __ldg(&epack[e + 2]);
        int p3 = __ldg(&epack[e + 3]);
        int r0 = (unsigned)p0 >> 28, r1 = (unsigned)p1 >> 28;
        int r2 = (unsigned)p2 >> 28, r3 = (unsigned)p3 >> 28;
        float4 v0 = __ldg((const float4*)(hb + ((size_t)(p0 & 0x0FFFFFFF) * 512 + (r0 << 7))));
        float4 v1 = __ldg((const float4*)(hb + ((size_t)(p1 & 0x0FFFFFFF) * 512 + (r1 << 7))));
        float4 v2 = __ldg((const float4*)(hb + ((size_t)(p2 & 0x0FFFFFFF) * 512 + (r2 << 7))));
        float4 v3 = __ldg((const float4*)(hb + ((size_t)(p3 & 0x0FFFFFFF) * 512 + (r3 << 7))));
        float ws0 = (r0 == 0) ? w0 : ((r0 == 1) ? w1 : w2);
        float ws1 = (r1 == 0) ? w0 : ((r1 == 1) ? w1 : w2);
        float ws2 = (r2 == 0) ? w0 : ((r2 == 1) ? w1 : w2);
        float ws3 = (r3 == 0) ? w0 : ((r3 == 1) ? w1 : w2);
        tx += v0.x * ws0 + v1.x * ws1 + v2.x * ws2 + v3.x * ws3;
        ty += v0.y * ws0 + v1.y * ws1 + v2.y * ws2 + v3.y * ws3;
        tz += v0.z * ws0 + v1.z * ws1 + v2.z * ws2 + v3.z * ws3;
        tw += v0.w * ws0 + v1.w * ws1 + v2.w * ws2 + v3.w * ws3;
    }
    for (; e < o1; e++) {
        int p0 = __ldg(&epack[e]);
        int r0 = (unsigned)p0 >> 28;
        float4 v0 = __ldg((const float4*)(hb + ((size_t)(p0 & 0x0FFFFFFF) * 512 + (r0 << 7))));
        float ws0 = (r0 == 0) ? w0 : ((r0 == 1) ? w1 : w2);
        tx += v0.x * ws0; ty += v0.y * ws0; tz += v0.z * ws0; tw += v0.w * ws0;
    }

    if (do_relu) {
        tx = fmaxf(tx, 0.f); ty = fmaxf(ty, 0.f);
        tz = fmaxf(tz, 0.f); tw = fmaxf(tw, 0.f);
    }
    size_t idx = (size_t)node * HH + lane * 4;
    if (write_f32) *(float4*)&xb[idx] = make_float4(tx, ty, tz, tw);
    bf16 h0 = __float2bfloat16(tx), h1 = __float2bfloat16(ty);
    bf16 h2 = __float2bfloat16(tz), h3 = __float2bfloat16(tw);
    __nv_bfloat162 hh0(h0, h1), hh1(h2, h3);
    *(uint2*)&xh[idx] = make_uint2(*(uint32_t*)&hh0, *(uint32_t*)&hh1);
    __nv_bfloat162 ll0(__float2bfloat16(tx - __bfloat162float(h0)),
                       __float2bfloat16(ty - __bfloat162float(h1)));
    __nv_bfloat162 ll1(__float2bfloat16(tz - __bfloat162float(h2)),
                       __float2bfloat16(tw - __bfloat162float(h3)));
    *(uint2*)&xl[idx] = make_uint2(*(uint32_t*)&ll0, *(uint32_t*)&ll1);
}

// ---------------- edge apply: warp/edge, relu(U[src]+V[dst]+be1) @ We2 + be2 ----------------
__global__ __launch_bounds__(256)
void edge_apply(const float* __restrict__ UV,
                const int* __restrict__ src, const int* __restrict__ dst,
                const float* __restrict__ be1, const float* __restrict__ We2,
                const float* __restrict__ be2, float* __restrict__ out, int E) {
    __shared__ float sBe1[128];
    __shared__ float sW2[384];
    const int tid = threadIdx.x, lane = tid & 31;
    if (tid < 128) sBe1[tid] = be1[tid];
    for (int v = tid; v < 384; v += 256) sW2[v] = We2[v];
    __syncthreads();
    int gw = (blockIdx.x * 256 + tid) >> 5;
    if (gw >= E) return;
    int s = src[gw], d = dst[gw];
    float4 u = __ldg((const float4*)(UV + (size_t)s * 256 + lane * 4));
    float4 v = __ldg((const float4*)(UV + (size_t)d * 256 + 128 + lane * 4));
    int c = lane * 4;
    float a0 = 0.f, a1 = 0.f, a2 = 0.f;
    float h;
    h = fmaxf(u.x + v.x + sBe1[c + 0], 0.f); a0 += h * sW2[(c + 0) * 3]; a1 += h * sW2[(c + 0) * 3 + 1]; a2 += h * sW2[(c + 0) * 3 + 2];
    h = fmaxf(u.y + v.y + sBe1[c + 1], 0.f); a0 += h * sW2[(c + 1) * 3]; a1 += h * sW2[(c + 1) * 3 + 1]; a2 += h * sW2[(c + 1) * 3 + 2];
    h = fmaxf(u.z + v.z + sBe1[c + 2], 0.f); a0 += h * sW2[(c + 2) * 3]; a1 += h * sW2[(c + 2) * 3 + 1]; a2 += h * sW2[(c + 2) * 3 + 2];
    h = fmaxf(u.w + v.w + sBe1[c + 3], 0.f); a0 += h * sW2[(c + 3) * 3]; a1 += h * sW2[(c + 3) * 3 + 1]; a2 += h * sW2[(c + 3) * 3 + 2];
#pragma unroll
    for (int o = 16; o; o >>= 1) {
        a0 += __shfl_xor_sync(0xFFFFFFFFu, a0, o);
        a1 += __shfl_xor_sync(0xFFFFFFFFu, a1, o);
        a2 += __shfl_xor_sync(0xFFFFFFFFu, a2, o);
    }
    if (lane == 0) {
        out[(size_t)gw * 3 + 0] = a0 + __ldg(&be2[0]);
        out[(size_t)gw * 3 + 1] = a1 + __ldg(&be2[1]);
        out[(size_t)gw * 3 + 2] = a2 + __ldg(&be2[2]);
    }
}

// ---------------- split fp32 -> bf16 hi/lo (layer-1 input only) ----------------
__global__ void split_bf16(const float* __restrict__ in, bf16* __restrict__ hi,
                           bf16* __restrict__ lo, int n4) {
    int i = blockIdx.x * blockDim.x + threadIdx.x;
    if (i >= n4) return;
    float4 v = ((const float4*)in)[i];
    bf16 h0 = __float2bfloat16(v.x), h1 = __float2bfloat16(v.y);
    bf16 h2 = __float2bfloat16(v.z), h3 = __float2bfloat16(v.w);
    ((__nv_bfloat162*)hi)[i * 2]     = __nv_bfloat162(h0, h1);
    ((__nv_bfloat162*)hi)[i * 2 + 1] = __nv_bfloat162(h2, h3);
    ((__nv_bfloat162*)lo)[i * 2]     = __nv_bfloat162(__float2bfloat16(v.x - __bfloat162float(h0)),
                                                      __float2bfloat16(v.y - __bfloat162float(h1)));
    ((__nv_bfloat162*)lo)[i * 2 + 1] = __nv_bfloat162(__float2bfloat16(v.z - __bfloat162float(h2)),
                                                      __float2bfloat16(v.w - __bfloat162float(h3)));
}

// ---------------- all weight packing in one kernel, upfront ----------------
__device__ __forceinline__ void pack_one(float v, bf16* __restrict__ Bh,
                                         bf16* __restrict__ Bl, int idx) {
    bf16 h = __float2bfloat16(v);
    Bh[idx] = h;
    Bl[idx] = __float2bfloat16(v - __bfloat162float(h));
}
__device__ __forceinline__ float layer_w(const float* __restrict__ W_root,
                                         const float* __restrict__ W_rel,
                                         int idx, int K) {
    int n = idx / K, k = idx % K;
    if (n < HH) return W_root[k * HH + n];
    return W_rel[((size_t)((n >> 7) - 1) * K + k) * HH + (n & 127)];
}
#define P1 (512 * INF)
#define P2 (512 * HH)
__global__ void pack_all(const float* __restrict__ Wr1, const float* __restrict__ Wrel1,
                         const float* __restrict__ Wr2, const float* __restrict__ Wrel2,
                         const float* __restrict__ Wr3, const float* __restrict__ Wrel3,
                         const float* __restrict__ We1,
                         bf16* B1h, bf16* B1l, bf16* B2h, bf16* B2l,
                         bf16* B3h, bf16* B3l, bf16* Weh, bf16* Wel) {
    int idx = blockIdx.x * blockDim.x + threadIdx.x;
    if (idx < P1) {
        pack_one(layer_w(Wr1, Wrel1, idx, INF), B1h, B1l, idx);
    } else if (idx < P1 + P2) {
        int i = idx - P1;
        pack_one(layer_w(Wr2, Wrel2, i, HH), B2h, B2l, i);
    } else if (idx < P1 + 2 * P2) {
        int i = idx - P1 - P2;
        pack_one(layer_w(Wr3, Wrel3, i, HH), B3h, B3l, i);
    } else if (idx < P1 + 2 * P2 + 256 * 128) {
        int i = idx - P1 - 2 * P2;
        int n = i / 128, k = i % 128;
        float v = (n < 128) ? We1[k * 128 + n] : We1[(128 + k) * 128 + (n - 128)];
        pack_one(v, Weh, Wel, i);
    }
}

// ---------------- node head: 64 nodes/block, weights in smem ----------------
__global__ __launch_bounds__(256)
void node_head_kernel(const float* __restrict__ x3, const float* __restrict__ Wn1,
                      const float* __restrict__ bn1, const float* __restrict__ Wn2,
                      const float* __restrict__ bn2, float* __restrict__ out) {
    __shared__ float sW1[128 * 64];
    __shared__ float sb1[64];
    __shared__ float sW2[128];
    __shared__ float sx[4][128];
    __shared__ float sPart[8][2];
    const int tid = threadIdx.x;
    const int team = tid >> 6, t = tid & 63;      // 4 teams of 64
    const int wid = tid >> 5, lane = tid & 31;
    for (int i = tid; i < 128 * 64; i += 256) sW1[i] = Wn1[i];
    if (tid < 64) sb1[tid] = bn1[tid];
    if (tid < 128) sW2[tid] = Wn2[tid];
    float b20 = __ldg(&bn2[0]), b21 = __ldg(&bn2[1]);
    __syncthreads();
    const int base = blockIdx.x * 64;
#pragma unroll 1
    for (int it = 0; it < 16; it++) {
        int node = base + it * 4 + team;
        bool ok = node < NN;
        if (ok) {
            sx[team][t]      = x3[(size_t)node * HH + t];
            sx[team][t + 64] = x3[(size_t)node * HH + t + 64];
        }
        __syncthreads();
        float p0 = 0.f, p1 = 0.f;
        if (ok) {
            float acc = sb1[t];
#pragma unroll
            for (int k = 0; k < 128; k++) acc += sx[team][k] * sW1[k * 64 + t];
            float hgt = fmaxf(acc, 0.f);
            p0 = hgt * sW2[t * 2 + 0];
            p1 = hgt * sW2[t * 2 + 1];
        }
#pragma unroll
        for (int o = 16; o; o >>= 1) {
            p0 += __shfl_xor_sync(0xFFFFFFFFu, p0, o);
            p1 += __shfl_xor_sync(0xFFFFFFFFu, p1, o);
        }
        if (lane == 0) { sPart[wid][0] = p0; sPart[wid][1] = p1; }
        __syncthreads();
        if (ok && t == 0) {
            out[(size_t)node * 2 + 0] = sPart[team * 2][0] + sPart[team * 2 + 1][0] + b20;
            out[(size_t)node * 2 + 1] = sPart[team * 2][1] + sPart[team * 2 + 1][1] + b21;
        }
        __syncthreads();
    }
}

// ---------------- launch ----------------
extern "C" void kernel_launch(void* const* d_in, const int* in_sizes, int n_in,
                              void* d_out, int out_size) {
    const float* x       = (const float*)d_in[0];
    const int*   ei      = (const int*)d_in[1];
    const int*   et      = (const int*)d_in[2];
    const float* W_rel1  = (const float*)d_in[3];
    const float* W_root1 = (const float*)d_in[4];
    const float* b1      = (const float*)d_in[5];
    const float* W_rel2  = (const float*)d_in[6];
    const float* W_root2 = (const float*)d_in[7];
    const float* b2      = (const float*)d_in[8];
    const float* W_rel3  = (const float*)d_in[9];
    const float* W_root3 = (const float*)d_in[10];
    const float* b3      = (const float*)d_in[11];
    const float* We1     = (const float*)d_in[12];
    const float* be1     = (const float*)d_in[13];
    const float* We2     = (const float*)d_in[14];
    const float* be2     = (const float*)d_in[15];
    const float* Wn1     = (const float*)d_in[16];
    const float* bn1     = (const float*)d_in[17];
    const float* Wn2     = (const float*)d_in[18];
    const float* bn2     = (const float*)d_in[19];

    const int E = in_sizes[2];
    const int* src = ei;
    const int* dst = ei + E;

    bf16 *B1h, *B1l, *B2h, *B2l, *B3h, *B3l, *Weh, *Wel, *xh, *xl;
    float *hcomb, *xb;
    int *deg, *offs, *cur, *cnt3, *epack;
    cudaGetSymbolAddress((void**)&B1h, g_B1h);
    cudaGetSymbolAddress((void**)&B1l, g_B1l);
    cudaGetSymbolAddress((void**)&B2h, g_B2h);
    cudaGetSymbolAddress((void**)&B2l, g_B2l);
    cudaGetSymbolAddress((void**)&B3h, g_B3h);
    cudaGetSymbolAddress((void**)&B3l, g_B3l);
    cudaGetSymbolAddress((void**)&Weh, g_Weh);
    cudaGetSymbolAddress((void**)&Wel, g_Wel);
    cudaGetSymbolAddress((void**)&xh, g_xh);
    cudaGetSymbolAddress((void**)&xl, g_xl);
    cudaGetSymbolAddress((void**)&hcomb, g_hcomb);
    cudaGetSymbolAddress((void**)&xb, g_xb);
    cudaGetSymbolAddress((void**)&deg, g_deg);
    cudaGetSymbolAddress((void**)&offs, g_offs);
    cudaGetSymbolAddress((void**)&cur, g_cur);
    cudaGetSymbolAddress((void**)&cnt3, g_cnt3);
    cudaGetSymbolAddress((void**)&epack, g_epack);

    cudaFuncSetAttribute(gemm_mma, cudaFuncAttributeMaxDynamicSharedMemorySize, DYN_SMEM);

    float* out = (float*)d_out;
    float* edge_out = out;
    float* node_out = out + (size_t)E * 3;

    const int aggBlocks = (NN * 32 + 255) / 256;
    dim3 gemmGrid(4, (NN + 127) / 128);
    dim3 uvGrid(2, (NN + 127) / 128);

    // ---- upfront: all weight packs + CSR build ----
    const int packTotal = P1 + 2 * P2 + 256 * 128;
    pack_all<<<(packTotal + 255) / 256, 256>>>(W_root1, W_rel1, W_root2, W_rel2,
                                               W_root3, W_rel3, We1,
                                               B1h, B1l, B2h, B2l, B3h, B3l, Weh, Wel);
    cudaMemsetAsync(deg, 0, NN * sizeof(int));
    cudaMemsetAsync(cur, 0, NN * sizeof(int));
    cudaMemsetAsync(cnt3, 0, NN * RR * sizeof(int));
    deg_kernel<<<(E + 255) / 256, 256>>>(dst, et, deg, cnt3, E);
    scan_kernel<<<1, 1024>>>(deg, offs);
    fill_kernel<<<(E + 255) / 256, 256>>>(src, dst, et, offs, cur, epack, E);

    // ---- layer 1 ----
    split_bf16<<<(NN * INF / 4 + 255) / 256, 256>>>(x, xh, xl, NN * INF / 4);
    gemm_mma<<<gemmGrid, 256, DYN_SMEM>>>(xh, xl, B1h, B1l, hcomb, NN, INF, 512);
    agg_combine<<<aggBlocks, 256>>>(hcomb, offs, epack, cnt3, b1, xb, xh, xl, 1, 0);

    // ---- layer 2 ----
    gemm_mma<<<gemmGrid, 256, DYN_SMEM>>>(xh, xl, B2h, B2l, hcomb, NN, HH, 512);
    agg_combine<<<aggBlocks, 256>>>(hcomb, offs, epack, cnt3, b2, xb, xh, xl, 1, 0);

    // ---- layer 3 (no relu; keep fp32 for node head) ----
    gemm_mma<<<gemmGrid, 256, DYN_SMEM>>>(xh, xl, B3h, B3l, hcomb, NN, HH, 512);
    agg_combine<<<aggBlocks, 256>>>(hcomb, offs, epack, cnt3, b3, xb, xh, xl, 0, 1);

    // ---- edge head: UV = x3 @ [We1_top|We1_bot], then per-edge apply ----
    gemm_mma<<<uvGrid, 256, DYN_SMEM>>>(xh, xl, Weh, Wel, hcomb, NN, HH, 256);
    edge_apply<<<(E * 32 + 255) / 256, 256>>>(hcomb, src, dst, be1, We2, be2, edge_out, E);

    // ---- node head ----
    node_head_kernel<<<(NN + 63) / 64, 256>>>(xb, Wn1, bn1, Wn2, bn2, node_out);
}